// round 1
// baseline (speedup 1.0000x reference)
#include <cuda_runtime.h>

// Shapes (fixed by the problem)
#define Dd 1024
#define Tt 32
#define Bb 16
#define Ss 128

// Scratch for the two projection GEMMs (allocation-free rule: __device__ globals)
__device__ float g_pi[Tt * Bb * Dd];   // [T*B, D]  pi = inputs @ W_in^T + b_in
__device__ float g_pc[Bb * Ss * Dd];   // [B*S, D]  pc = context @ W_ctx^T + b_ctx

// ---------------------------------------------------------------------------
// GEMM: C[m,n] = sum_k A[m,k] * W[n,k] + bias[n]   (both row-major, NT gemm)
// One fused grid: blocks [0,64) do pi (M=512), blocks [64,320) do pc (M=2048).
// BM=128, BN=64, BK=16, 256 threads, 8x4 microtile per thread.
// ---------------------------------------------------------------------------
#define BM 128
#define BN 64
#define BK 16

__global__ void __launch_bounds__(256) gemm_kernel(
    const float* __restrict__ inputs, const float* __restrict__ context,
    const float* __restrict__ W_in,  const float* __restrict__ b_in,
    const float* __restrict__ W_ctx, const float* __restrict__ b_ctx)
{
    const float* A; const float* W; const float* bias; float* Cout;
    int tile;
    if (blockIdx.x < 64) { A = inputs;  W = W_in;  bias = b_in;  Cout = g_pi; tile = blockIdx.x; }
    else                 { A = context; W = W_ctx; bias = b_ctx; Cout = g_pc; tile = blockIdx.x - 64; }
    const int bm = (tile >> 4) * BM;   // 16 N-tiles of 64 across D=1024
    const int bn = (tile & 15) * BN;

    __shared__ __align__(16) float As[BK][BM + 4];   // transposed, padded
    __shared__ __align__(16) float Bs[BK][BN + 4];

    const int tid = threadIdx.x;
    const int ar  = tid >> 2;          // 0..63
    const int ac4 = tid & 3;           // float4 column within BK=16

    const float* aP0 = A + (size_t)(bm + ar) * Dd + ac4 * 4;
    const float* aP1 = aP0 + 64 * Dd;
    const float* bP  = W + (size_t)(bn + ar) * Dd + ac4 * 4;

    const int tx = tid & 15;           // 4 output cols:  bn + tx*4 ..
    const int ty = tid >> 4;           // 8 output rows:  bm + ty*8 ..

    float acc[8][4];
    #pragma unroll
    for (int i = 0; i < 8; i++)
        #pragma unroll
        for (int j = 0; j < 4; j++) acc[i][j] = 0.f;

    float4 a0 = *(const float4*)aP0;
    float4 a1 = *(const float4*)aP1;
    float4 b0 = *(const float4*)bP;

    for (int k0 = 0; k0 < Dd; k0 += BK) {
        // store current tile (transposed) to smem
        As[ac4*4+0][ar]    = a0.x;  As[ac4*4+1][ar]    = a0.y;
        As[ac4*4+2][ar]    = a0.z;  As[ac4*4+3][ar]    = a0.w;
        As[ac4*4+0][ar+64] = a1.x;  As[ac4*4+1][ar+64] = a1.y;
        As[ac4*4+2][ar+64] = a1.z;  As[ac4*4+3][ar+64] = a1.w;
        Bs[ac4*4+0][ar]    = b0.x;  Bs[ac4*4+1][ar]    = b0.y;
        Bs[ac4*4+2][ar]    = b0.z;  Bs[ac4*4+3][ar]    = b0.w;
        __syncthreads();

        // prefetch next tile into registers (overlaps with compute below)
        if (k0 + BK < Dd) {
            a0 = *(const float4*)(aP0 + k0 + BK);
            a1 = *(const float4*)(aP1 + k0 + BK);
            b0 = *(const float4*)(bP  + k0 + BK);
        }

        #pragma unroll
        for (int kk = 0; kk < BK; kk++) {
            float4 af0 = *(const float4*)&As[kk][ty * 8];
            float4 af1 = *(const float4*)&As[kk][ty * 8 + 4];
            float4 bf  = *(const float4*)&Bs[kk][tx * 4];
            float aa[8] = {af0.x, af0.y, af0.z, af0.w, af1.x, af1.y, af1.z, af1.w};
            float bb[4] = {bf.x, bf.y, bf.z, bf.w};
            #pragma unroll
            for (int i = 0; i < 8; i++)
                #pragma unroll
                for (int j = 0; j < 4; j++)
                    acc[i][j] = fmaf(aa[i], bb[j], acc[i][j]);
        }
        __syncthreads();
    }

    const float4 bv = *(const float4*)(bias + bn + tx * 4);
    #pragma unroll
    for (int i = 0; i < 8; i++) {
        float4 o;
        o.x = acc[i][0] + bv.x;
        o.y = acc[i][1] + bv.y;
        o.z = acc[i][2] + bv.z;
        o.w = acc[i][3] + bv.w;
        *(float4*)(Cout + (size_t)(bm + ty * 8 + i) * Dd + bn + tx * 4) = o;
    }
}

// ---------------------------------------------------------------------------
// Fused scores -> softmax -> weighted context sum.
// One CTA per (t,b).  8 warps; each warp computes 16 of the 128 scores
// (full-D dot with swish), then a block softmax, then each thread accumulates
// one float4 of the output over all 128 source positions.
// b_one is omitted: softmax is shift-invariant, so both outputs are identical.
// ---------------------------------------------------------------------------
__global__ void __launch_bounds__(256) attn_kernel(
    const float* __restrict__ context,
    const float* __restrict__ w_one,
    float* __restrict__ out)          // [0, T*B*D): attn_context ; then [.., +T*B*S): attn
{
    const int tb = blockIdx.x;        // t*16 + b
    const int b  = tb & (Bb - 1);

    __shared__ float4 s_pi[Dd / 4];
    __shared__ float4 s_w[Dd / 4];
    __shared__ float  s_sc[Ss];
    __shared__ float  s_red[8];

    const int tid  = threadIdx.x;
    const int lane = tid & 31;
    const int warp = tid >> 5;

    s_pi[tid] = ((const float4*)(g_pi + (size_t)tb * Dd))[tid];
    s_w[tid]  = ((const float4*)w_one)[tid];
    __syncthreads();

    // ---- scores ----
    const float* pcb = g_pc + (size_t)b * Ss * Dd;
    for (int s = warp; s < Ss; s += 8) {
        const float4* row = (const float4*)(pcb + (size_t)s * Dd);
        float acc = 0.f;
        #pragma unroll
        for (int i = 0; i < 8; i++) {
            const int idx = i * 32 + lane;
            float4 pcv = row[idx];
            float4 piv = s_pi[idx];
            float4 wv  = s_w[idx];
            float c;
            c = piv.x + pcv.x; acc += __fdividef(c, 1.f + __expf(-c)) * wv.x;
            c = piv.y + pcv.y; acc += __fdividef(c, 1.f + __expf(-c)) * wv.y;
            c = piv.z + pcv.z; acc += __fdividef(c, 1.f + __expf(-c)) * wv.z;
            c = piv.w + pcv.w; acc += __fdividef(c, 1.f + __expf(-c)) * wv.w;
        }
        #pragma unroll
        for (int o = 16; o > 0; o >>= 1)
            acc += __shfl_xor_sync(0xffffffffu, acc, o);
        if (lane == 0) s_sc[s] = acc;
    }
    __syncthreads();

    // ---- softmax over 128 scores (threads 0..127 own one score each) ----
    float v = (tid < Ss) ? s_sc[tid] : -1e30f;
    float m = v;
    #pragma unroll
    for (int o = 16; o > 0; o >>= 1)
        m = fmaxf(m, __shfl_xor_sync(0xffffffffu, m, o));
    if (lane == 0 && warp < 4) s_red[warp] = m;
    __syncthreads();
    const float mx = fmaxf(fmaxf(s_red[0], s_red[1]), fmaxf(s_red[2], s_red[3]));
    float p = (tid < Ss) ? __expf(v - mx) : 0.f;
    float sum = p;
    #pragma unroll
    for (int o = 16; o > 0; o >>= 1)
        sum += __shfl_xor_sync(0xffffffffu, sum, o);
    if (lane == 0 && warp < 4) s_red[4 + warp] = sum;
    __syncthreads();
    const float tot = s_red[4] + s_red[5] + s_red[6] + s_red[7];
    const float inv = __fdividef(1.f, tot);
    if (tid < Ss) {
        const float a = p * inv;
        s_sc[tid] = a;
        out[(size_t)Tt * Bb * Dd + (size_t)tb * Ss + tid] = a;   // attn output
    }
    __syncthreads();

    // ---- attn_context[t,b,:] = sum_s attn[s] * context[b,s,:] ----
    const float* ctxb = context + (size_t)b * Ss * Dd;
    float4 acc4 = make_float4(0.f, 0.f, 0.f, 0.f);
    #pragma unroll 8
    for (int s = 0; s < Ss; s++) {
        const float  a = s_sc[s];
        const float4 c = ((const float4*)(ctxb + (size_t)s * Dd))[tid];
        acc4.x += a * c.x;
        acc4.y += a * c.y;
        acc4.z += a * c.z;
        acc4.w += a * c.w;
    }
    ((float4*)(out + (size_t)tb * Dd))[tid] = acc4;
}

// ---------------------------------------------------------------------------
extern "C" void kernel_launch(void* const* d_in, const int* in_sizes, int n_in,
                              void* d_out, int out_size) {
    const float* inputs  = (const float*)d_in[0];
    const float* context = (const float*)d_in[1];
    const float* W_in    = (const float*)d_in[2];
    const float* b_in    = (const float*)d_in[3];
    const float* W_ctx   = (const float*)d_in[4];
    const float* b_ctx   = (const float*)d_in[5];
    const float* w_one   = (const float*)d_in[6];
    // d_in[7] = b_one: softmax is shift-invariant -> no effect on either output.
    float* out = (float*)d_out;

    gemm_kernel<<<320, 256>>>(inputs, context, W_in, b_in, W_ctx, b_ctx);
    attn_kernel<<<Tt * Bb, 256>>>(context, w_one, out);
}